// round 17
// baseline (speedup 1.0000x reference)
#include <cuda_runtime.h>
#include <cuda_bf16.h>

#define T_STEPS 256
#define BATCH   128
#define DIM_IN  512
#define HID     512
#define NQ      8
#define QDIM    256   // 2^8
#define NCHUNK  32    // 8 timesteps per chunk

// ---------------- scratch (no allocations allowed) ----------------
__device__ float4 g_xdot[T_STEPS * BATCH];   // per (t,b): raw dots for f,i,g,o
// per gate: [0]=wsum  [1]=b0-phi  [2]=alpha/2  [3]=R/2  [4]=alpha  [5]=R
__device__ float  g_par[4][6];

__device__ __forceinline__ float2 cmul(float2 a, float2 b) {
    return make_float2(a.x * b.x - a.y * b.y, a.x * b.y + a.y * b.x);
}
__device__ __forceinline__ float2 cadd(float2 a, float2 b) {
    return make_float2(a.x + b.x, a.y + b.y);
}
__device__ __forceinline__ float htanh(float x) {
    float y;
    asm("tanh.approx.f32 %0, %1;" : "=f"(y) : "f"(x));
    return y;
}
__device__ __forceinline__ float dot4(float4 w, float4 x) {
    return w.x * x.x + w.y * x.y + w.z * x.z + w.w * x.w;
}

// ---------------- circuit: simulate one variational circuit ----------------
// Statevector-simulates columns 0 and 128 of the 2-layer circuit, reduces to
// expval(theta) = alpha + R*cos(theta - phi), plus wsum and b0-phi.
__device__ void circuit_block(int g, const float* __restrict__ P,
                              const float* __restrict__ W, const float* __restrict__ bv)
{
    __shared__ float2 a0[QDIM], a1[QDIM];
    __shared__ float  r0[QDIM], r1[QDIM], r2[QDIM];
    int d = threadIdx.x;

    a0[d] = make_float2(d == 0 ? 1.f : 0.f, 0.f);
    a1[d] = make_float2(d == QDIM / 2 ? 1.f : 0.f, 0.f);

    for (int l = 0; l < 2; l++) {
        for (int w = 0; w < NQ; w++) {
            const float* p = P + (l * NQ + w) * 3;
            float phi = p[0], th = p[1], om = p[2];
            float c, s;  __sincosf(0.5f * th, &s, &c);
            float cap, sap; __sincosf(0.5f * (phi + om), &sap, &cap);
            float cbm, sbm; __sincosf(0.5f * (phi - om), &sbm, &cbm);
            float2 m00 = make_float2(cap * c, -sap * c);     // ep*c
            float2 m01 = make_float2(-cbm * s, -sbm * s);    // -em*s
            float2 m10 = make_float2(cbm * s, -sbm * s);     // conj(em)*s
            float2 m11 = make_float2(cap * c, sap * c);      // conj(ep)*c

            int p7 = 7 - w;
            int mask = 1 << p7;
            int bit = (d >> p7) & 1;
            __syncthreads();
            float2 me0 = a0[d], pa0 = a0[d ^ mask];
            float2 me1 = a1[d], pa1 = a1[d ^ mask];
            __syncthreads();
            float2 n0, n1;
            if (!bit) {
                n0 = cadd(cmul(m00, me0), cmul(m01, pa0));
                n1 = cadd(cmul(m00, me1), cmul(m01, pa1));
            } else {
                n0 = cadd(cmul(m10, pa0), cmul(m11, me0));
                n1 = cadd(cmul(m10, pa1), cmul(m11, me1));
            }
            a0[d] = n0; a1[d] = n1;
        }
        for (int w = 0; w < NQ - 1; w++) {
            int pc = 7 - w, pt = 6 - w;
            __syncthreads();
            int src = ((d >> pc) & 1) ? (d ^ (1 << pt)) : d;
            float2 v0 = a0[src], v1 = a1[src];
            __syncthreads();
            a0[d] = v0; a1[d] = v1;
        }
    }
    __syncthreads();

    float z = (d < QDIM / 2) ? 1.f : -1.f;
    float2 c0 = a0[d], c1 = a1[d];
    r0[d] = z * (c0.x * c0.x + c0.y * c0.y);
    r1[d] = z * (c1.x * c1.x + c1.y * c1.y);
    r2[d] = z * (c0.y * c1.x - c0.x * c1.y);
    __syncthreads();
    for (int off = QDIM / 2; off; off >>= 1) {
        if (d < off) { r0[d] += r0[d + off]; r1[d] += r1[d + off]; r2[d] += r2[d + off]; }
        __syncthreads();
    }
    float S00 = r0[0], S11 = r1[0], S01 = r2[0];
    __syncthreads();

    r0[d] = W[512 + d] + W[512 + QDIM + d];
    __syncthreads();
    for (int off = QDIM / 2; off; off >>= 1) {
        if (d < off) r0[d] += r0[d + off];
        __syncthreads();
    }
    if (d == 0) {
        float alpha = 0.5f * (S00 + S11);
        float beta  = 0.5f * (S00 - S11);
        float gamma = -S01;
        float R   = sqrtf(beta * beta + gamma * gamma);
        float phi = atan2f(gamma, beta);
        g_par[g][0] = r0[0];          // wsum
        g_par[g][1] = bv[0] - phi;    // theta offset (added in scan)
        g_par[g][2] = 0.5f * alpha;
        g_par[g][3] = 0.5f * R;
        g_par[g][4] = alpha;
        g_par[g][5] = R;
    }
}

// ---------------- prep: circuit (blocks 0-3) + xdot, 2 rows per warp (R8 form) ----------------
__global__ void __launch_bounds__(256, 4) prep_kernel(
    const float* __restrict__ X,
    const float* __restrict__ Wf, const float* __restrict__ Wi,
    const float* __restrict__ Wg, const float* __restrict__ Wo,
    const float* __restrict__ bfv, const float* __restrict__ biv,
    const float* __restrict__ bgv, const float* __restrict__ bov,
    const float* __restrict__ Pf, const float* __restrict__ Pi,
    const float* __restrict__ Pg, const float* __restrict__ Po)
{
    if (blockIdx.x < 4) {
        int g = blockIdx.x;
        const float* P  = (g == 0) ? Pf : (g == 1) ? Pi : (g == 2) ? Pg : Po;
        const float* W  = (g == 0) ? Wf : (g == 1) ? Wi : (g == 2) ? Wg : Wo;
        const float* bv = (g == 0) ? bfv : (g == 1) ? biv : (g == 2) ? bgv : bov;
        circuit_block(g, P, W, bv);
        return;
    }

    int j    = blockIdx.x - 4;           // 0..2047 ; 16 rows per block
    int warp = threadIdx.x >> 5;
    int lane = threadIdx.x & 31;
    int rA   = j * 16 + warp * 2;        // rows rA, rA+1

    const float4* xa = (const float4*)(X + (size_t)rA * DIM_IN);
    const float4* xb = xa + (DIM_IN / 4);

    // front-batch all 8 X loads (MLP=8)
    float4 A0 = xa[lane], A1 = xa[lane + 32], A2 = xa[lane + 64], A3 = xa[lane + 96];
    float4 B0 = xb[lane], B1 = xb[lane + 32], B2 = xb[lane + 64], B3 = xb[lane + 96];

    float fA, fB, iA, iB, gA, gB, oA, oB;

#define GDOT(Wp, dA, dB)                                                          \
    {                                                                             \
        const float4* w4 = (const float4*)(Wp);                                   \
        float4 w0 = __ldg(w4 + lane),      w1 = __ldg(w4 + lane + 32),            \
               w2 = __ldg(w4 + lane + 64), w3 = __ldg(w4 + lane + 96);            \
        dA = dot4(w0, A0) + dot4(w1, A1) + dot4(w2, A2) + dot4(w3, A3);           \
        dB = dot4(w0, B0) + dot4(w1, B1) + dot4(w2, B2) + dot4(w3, B3);           \
    }
    GDOT(Wf, fA, fB)
    GDOT(Wi, iA, iB)
    GDOT(Wg, gA, gB)
    GDOT(Wo, oA, oB)
#undef GDOT

#pragma unroll
    for (int o = 16; o; o >>= 1) {
        fA += __shfl_xor_sync(0xffffffffu, fA, o);
        fB += __shfl_xor_sync(0xffffffffu, fB, o);
        iA += __shfl_xor_sync(0xffffffffu, iA, o);
        iB += __shfl_xor_sync(0xffffffffu, iB, o);
        gA += __shfl_xor_sync(0xffffffffu, gA, o);
        gB += __shfl_xor_sync(0xffffffffu, gB, o);
        oA += __shfl_xor_sync(0xffffffffu, oA, o);
        oB += __shfl_xor_sync(0xffffffffu, oB, o);
    }
    if (lane == 0) {
        g_xdot[rA]     = make_float4(fA, iA, gA, oA);
        g_xdot[rA + 1] = make_float4(fB, iB, gB, oB);
    }
}

// ---------------- scanout: flag-decoupled scan + output write ----------------
// One block per batch element. After ONE init barrier, roles diverge forever
// (no further __syncthreads — the R13 lesson). Thread 0 runs the chain and
// publishes each 8-step chunk into a 4-deep smem ring via volatile flag +
// __threadfence_block. Writer warps {1,2,3,5,6,7} poll the flag and stream
// rows out; warp 4 idles (it shares SMSP0 with the compute warp).
__device__ __forceinline__ float ptanh_half(float x) {   // |x| <= ~0.55
    float t = x * x;
    float p = fmaf(t, -17.f / 315.f, 2.f / 15.f);
    p = fmaf(t, p, -1.f / 3.f);
    p = fmaf(t, p, 1.f);
    return x * p;
}

__global__ void __launch_bounds__(256) scanout_kernel(float4* __restrict__ out)
{
    const unsigned OUT4 = (unsigned)T_STEPS * BATCH * (HID / 4); // 4,194,304
    const unsigned HB4  = (unsigned)BATCH * (HID / 4);           // 16,384

    int b    = blockIdx.x;        // batch element
    int tid  = threadIdx.x;
    int warp = tid >> 5;
    int lane = tid & 31;

    __shared__ float sH[4][8];            // 4-deep chunk ring
    __shared__ float sHx, sCx;            // final h, c
    __shared__ volatile int s_wprog;      // chunks published (33 = finals ready)
    __shared__ volatile int s_wdone[8];   // per-warp chunks written

    if (tid == 0) s_wprog = 0;
    if (tid < 8) s_wdone[tid] = (tid == 0 || tid == 4) ? (1 << 30) : 0;
    __syncthreads();                      // the ONLY block barrier

    // ================= compute role: thread 0 =================
    if (tid == 0) {
        float ws_f = g_par[0][0], A2_f = g_par[0][2], R2_f = g_par[0][3];
        float ws_i = g_par[1][0], A2_i = g_par[1][2], R2_i = g_par[1][3];
        float ws_g = g_par[2][0], A_g  = g_par[2][4], R_g  = g_par[2][5];
        float ws_o = g_par[3][0], A2_o = g_par[3][2], R2_o = g_par[3][3];
        float off_f = g_par[0][1], off_i = g_par[1][1], off_g = g_par[2][1], off_o = g_par[3][1];

        float H = 0.f, C = 0.f;
        const float4* Xd = g_xdot;

#define LOADADJ(t) \
    ({ float4 v_ = Xd[(t) * BATCH + b]; \
       v_.x += off_f; v_.y += off_i; v_.z += off_g; v_.w += off_o; v_; })

        float4 q[8];
#pragma unroll
        for (int j = 0; j < 8; j++) q[j] = LOADADJ(j);

#define STEP(xd, kk, jj)                                              \
    {                                                                 \
        float cf = __cosf(fmaf(H, ws_f, (xd).x));                     \
        float ci = __cosf(fmaf(H, ws_i, (xd).y));                     \
        float cg = __cosf(fmaf(H, ws_g, (xd).z));                     \
        float co = __cosf(fmaf(H, ws_o, (xd).w));                     \
        float fv = fmaf(ptanh_half(fmaf(R2_f, cf, A2_f)), 0.5f, 0.5f);\
        float iv = fmaf(ptanh_half(fmaf(R2_i, ci, A2_i)), 0.5f, 0.5f);\
        float gv = htanh(fmaf(R_g, cg, A_g));                         \
        float ov = fmaf(ptanh_half(fmaf(R2_o, co, A2_o)), 0.5f, 0.5f);\
        C = fmaf(fv, C, iv * gv);                                     \
        H = ov * htanh(C);                                            \
        sH[(kk) & 3][jj] = H;                                         \
    }

#pragma unroll 1
        for (int k = 0; k < NCHUNK; k++) {
            // backpressure: slot (k&3) must be drained (writers are ~6x faster;
            // this almost never spins)
            if (k >= 4) {
#pragma unroll
                for (int w = 1; w < 8; w++)
                    while (s_wdone[w] < k - 3) __nanosleep(32);
            }
            int t0 = k * 8;
#pragma unroll
            for (int j = 0; j < 8; j++) {
                float4 cur = q[j];
                if (t0 + 8 + j < T_STEPS) q[j] = LOADADJ(t0 + 8 + j);
                STEP(cur, k, j);
            }
            __threadfence_block();           // release ring slot
            s_wprog = k + 1;
        }
        sHx = sH[(NCHUNK - 1) & 3][7];
        sCx = C;
        __threadfence_block();
        s_wprog = NCHUNK + 1;                // finals sentinel
#undef STEP
#undef LOADADJ
        return;
    }

    // lanes 1-31 of warp 0, and all of warp 4 (shares SMSP0 with compute): idle
    if (warp == 0 || warp == 4) return;

    // ================= writer role: warps 1,2,3,5,6,7 =================
    {
        int wi   = (warp < 4) ? (warp - 1) : (warp - 2);   // 0..5
        int wtid = wi * 32 + lane;                         // 0..191

#pragma unroll 1
        for (int c = 0; c < NCHUNK; c++) {
            while (s_wprog < c + 1) __nanosleep(32);
            __threadfence_block();           // acquire ring slot
            const float* hs = sH[c & 3];
            unsigned rowbase = (unsigned)c * 8u;
#pragma unroll 1
            for (int u = wtid; u < 1024; u += 192) {
                int tl  = u >> 7;            // 0..7
                int pos = u & 127;           // float4 within the 512-wide row
                float v = hs[tl];
                unsigned idx = ((rowbase + tl) * BATCH + (unsigned)b) * (HID / 4) + pos;
                __stcs(out + idx, make_float4(v, v, v, v));
            }
            if (lane == 0) s_wdone[warp] = c + 1;
        }

        // tail: hx, cx
        while (s_wprog < NCHUNK + 1) __nanosleep(32);
        __threadfence_block();
        float hfin = sHx, cfin = sCx;
#pragma unroll 1
        for (int u = wtid; u < 256; u += 192) {
            unsigned idx = (u < 128)
                ? OUT4 + (unsigned)b * (HID / 4) + u
                : OUT4 + HB4 + (unsigned)b * (HID / 4) + (u - 128);
            float v = (u < 128) ? hfin : cfin;
            __stcs(out + idx, make_float4(v, v, v, v));
        }
    }
}

// ---------------- launch ----------------
extern "C" void kernel_launch(void* const* d_in, const int* in_sizes, int n_in,
                              void* d_out, int out_size)
{
    const float* X  = (const float*)d_in[0];
    const float* Wf = (const float*)d_in[1];
    const float* bf = (const float*)d_in[2];
    const float* Pf = (const float*)d_in[3];
    const float* Wi = (const float*)d_in[4];
    const float* bi = (const float*)d_in[5];
    const float* Pi = (const float*)d_in[6];
    const float* Wg = (const float*)d_in[7];
    const float* bg = (const float*)d_in[8];
    const float* Pg = (const float*)d_in[9];
    const float* Wo = (const float*)d_in[10];
    const float* bo = (const float*)d_in[11];
    const float* Po = (const float*)d_in[12];

    // blocks 0-3: circuits; blocks 4..2051: xdot (32768 rows / 16 rows per block)
    prep_kernel<<<4 + (T_STEPS * BATCH) / 16, 256>>>(
        X, Wf, Wi, Wg, Wo, bf, bi, bg, bo, Pf, Pi, Pg, Po);

    // one block per batch element; scan + output streaming, flag-decoupled
    scanout_kernel<<<BATCH, 256>>>((float4*)d_out);
}